// round 6
// baseline (speedup 1.0000x reference)
#include <cuda_runtime.h>
#include <cuda_bf16.h>
#include <cstdint>

#define NN 50000
#define EE 800000
#define HIDC 128
#define OUTC 64
#define EPSF 1e-5f
#define NCHUNK 196   // ceil(NN/256)

// ---------------- scratch (device globals) ----------------
__device__ float g_deg[NN];
__device__ float g_dinv[NN];
__device__ float g_h[(size_t)NN * HIDC];
__device__ float g_sum[HIDC];
__device__ float g_sumsq[HIDC];
// CSR scratch
__device__ int   g_cnt[NN];
__device__ int   g_bsum[NCHUNK];
__device__ int   g_boff[NCHUNK];
__device__ int   g_rowptr[NN + 1];
__device__ int   g_cursor[NN];
__device__ int   g_csr_src[EE];
__device__ float g_csr_w[EE];
// split-bf16 weights, pre-transposed: [N=128][K=256], K-major rows
__device__ __nv_bfloat16 g_w1hi[128 * 256];
__device__ __nv_bfloat16 g_w1lo[128 * 256];
__device__ __nv_bfloat16 g_w2hi[128 * 256];
__device__ __nv_bfloat16 g_w2lo[128 * 256];
__device__ float g_bias2[128];

// ---------------- mma / ldmatrix helpers ----------------
__device__ __forceinline__ uint32_t smem_u32(const void* p) {
    uint32_t a;
    asm("{ .reg .u64 t; cvta.to.shared.u64 t, %1; cvt.u32.u64 %0, t; }" : "=r"(a) : "l"(p));
    return a;
}
__device__ __forceinline__ void ldsm4(uint32_t* r, uint32_t addr) {
    asm volatile("ldmatrix.sync.aligned.m8n8.x4.shared.b16 {%0,%1,%2,%3}, [%4];"
                 : "=r"(r[0]), "=r"(r[1]), "=r"(r[2]), "=r"(r[3]) : "r"(addr));
}
__device__ __forceinline__ void mma_bf16(float* c, const uint32_t* a, const uint32_t* b) {
    asm volatile("mma.sync.aligned.m16n8k16.row.col.f32.bf16.bf16.f32 "
                 "{%0,%1,%2,%3}, {%4,%5,%6,%7}, {%8,%9}, {%0,%1,%2,%3};"
                 : "+f"(c[0]), "+f"(c[1]), "+f"(c[2]), "+f"(c[3])
                 : "r"(a[0]), "r"(a[1]), "r"(a[2]), "r"(a[3]), "r"(b[0]), "r"(b[1]));
}

// ---------------- small kernels ----------------
__global__ void k_zero_small() {
    int i = blockIdx.x * blockDim.x + threadIdx.x;
    if (i < NN) { g_deg[i] = 0.f; g_cnt[i] = 0; }
    if (i < HIDC) { g_sum[i] = 0.f; g_sumsq[i] = 0.f; }
}

__global__ void k_prep(const int* __restrict__ src, const int* __restrict__ dst) {
    int e = blockIdx.x * blockDim.x + threadIdx.x;
    if (e < EE) {
        atomicAdd(&g_deg[src[e]], 1.0f);
        atomicAdd(&g_cnt[dst[e]], 1);
    }
}

// fused: dinv + per-chunk count sums
__global__ void k_csrprep() {
    __shared__ int s[256];
    int c = blockIdx.x * 256 + threadIdx.x;
    int v = 0;
    if (c < NN) {
        v = g_cnt[c];
        float d = g_deg[c];
        g_dinv[c] = (d > 0.5f) ? rsqrtf(d) : 0.f;
    }
    s[threadIdx.x] = v;
    __syncthreads();
    for (int off = 128; off > 0; off >>= 1) {
        if (threadIdx.x < off) s[threadIdx.x] += s[threadIdx.x + off];
        __syncthreads();
    }
    if (threadIdx.x == 0) g_bsum[blockIdx.x] = s[0];
}

__global__ void k_bscan() {
    __shared__ int s[256];
    int t = threadIdx.x;
    int v = (t < NCHUNK) ? g_bsum[t] : 0;
    s[t] = v;
    __syncthreads();
    for (int off = 1; off < 256; off <<= 1) {
        int u = (t >= off) ? s[t - off] : 0;
        __syncthreads();
        s[t] += u;
        __syncthreads();
    }
    if (t < NCHUNK) g_boff[t] = s[t] - v;
    if (t == 0) g_rowptr[NN] = EE;
}

__global__ void k_chunkscan() {
    __shared__ int s[256];
    int c = blockIdx.x * 256 + threadIdx.x;
    int v = (c < NN) ? g_cnt[c] : 0;
    s[threadIdx.x] = v;
    __syncthreads();
    for (int off = 1; off < 256; off <<= 1) {
        int t = (threadIdx.x >= off) ? s[threadIdx.x - off] : 0;
        __syncthreads();
        s[threadIdx.x] += t;
        __syncthreads();
    }
    if (c < NN) {
        int excl = g_boff[blockIdx.x] + s[threadIdx.x] - v;
        g_rowptr[c] = excl;
        g_cursor[c] = excl;
    }
}

__global__ void k_fill(const int* __restrict__ src, const int* __restrict__ dst) {
    int e = blockIdx.x * blockDim.x + threadIdx.x;
    if (e < EE) {
        int s = src[e], d = dst[e];
        int p = atomicAdd(&g_cursor[d], 1);
        g_csr_src[p] = s;
        g_csr_w[p] = g_dinv[s];
    }
}

// ---------------- weight prep: transpose + split to bf16 hi/lo ----------------
__global__ void k_prepw(const float* __restrict__ W1_0, const float* __restrict__ W1_1,
                        const float* __restrict__ Wmu0, const float* __restrict__ Wmu1,
                        const float* __restrict__ Wls0, const float* __restrict__ Wls1,
                        const float* __restrict__ bmu, const float* __restrict__ bls) {
    int idx = blockIdx.x * blockDim.x + threadIdx.x;
    if (idx < 65536) {
        int stage = idx >> 15;
        int r = idx & 32767;
        int j = r >> 8, k = r & 255;
        float w;
        if (stage == 0) {
            w = (k < 128) ? W1_0[k * HIDC + j] : W1_1[(k - 128) * HIDC + j];
        } else {
            if (j < 64) w = (k < 128) ? Wmu0[k * OUTC + j] : Wmu1[(k - 128) * OUTC + j];
            else        w = (k < 128) ? Wls0[k * OUTC + (j - 64)] : Wls1[(k - 128) * OUTC + (j - 64)];
        }
        __nv_bfloat16 hi = __float2bfloat16(w);
        __nv_bfloat16 lo = __float2bfloat16(w - __bfloat162float(hi));
        if (stage == 0) { g_w1hi[r] = hi; g_w1lo[r] = lo; }
        else            { g_w2hi[r] = hi; g_w2lo[r] = lo; }
    }
    if (blockIdx.x == 0 && threadIdx.x < 128) {
        int j = threadIdx.x;
        g_bias2[j] = (j < 64) ? bmu[j] : bls[j - 64];
    }
}

// ---------------- fused gather + HMMA split-bf16 GEMM ----------------
// Per CTA: 128 output rows. K=256 in two 128-chunks:
//   chunk 0 (A0): stage0 -> X rows;          stage1 -> bnrelu(g_h) rows
//   chunk 1 (A1): gathered neighbor sum (CSR) of the same source, done in-kernel
// stage0 epilogue: write g_h + fused BN column sums into g_sum/g_sumsq
// stage1 epilogue: write [mu | logstd]
#define TSTRIDE 272
#define TILE_B (128 * TSTRIDE)
#define OFF_AHI 0
#define OFF_ALO TILE_B
#define OFF_BHI (2 * TILE_B)
#define OFF_BLO (3 * TILE_B)
#define SMEM_TOT (4 * TILE_B)

__global__ void __launch_bounds__(256) k_tgemm(const float* __restrict__ Xext,
                                               const float* __restrict__ biasExt,
                                               const float* __restrict__ gamma,
                                               const float* __restrict__ beta,
                                               float* __restrict__ outExt, int stage) {
    extern __shared__ char sm[];
    __shared__ float s_cs[128], s_cq[128];   // stage0: column sums; stage1: scale/shift
    uint32_t sb = smem_u32(sm);
    int t = threadIdx.x;
    int row0 = blockIdx.x * 128;

    if (stage == 0) {
        if (t < 128) { s_cs[t] = 0.f; s_cq[t] = 0.f; }
    } else {
        if (t < 128) {
            float mean = g_sum[t] * (1.0f / NN);
            float var = fmaxf(g_sumsq[t] * (1.0f / NN) - mean * mean, 0.f);
            float sc = gamma[t] * rsqrtf(var + EPSF);
            s_cs[t] = sc;                      // scale
            s_cq[t] = beta[t] - mean * sc;     // shift
        }
        __syncthreads();
    }

    const float* Asrc = stage ? g_h : Xext;
    const __nv_bfloat16* Whi = stage ? g_w2hi : g_w1hi;
    const __nv_bfloat16* Wlo = stage ? g_w2lo : g_w1lo;
    const float* bias = stage ? g_bias2 : biasExt;

    int w = t >> 5, lane = t & 31;
    int warp_m = (w >> 1) * 32, warp_n = (w & 1) * 64;
    int gid = lane >> 2, tig = lane & 3;

    int arow = (lane & 7) + ((lane >> 3) & 1) * 8;
    int akoff = (lane >> 4) * 8;
    uint32_t aoff0 = (uint32_t)(warp_m + arow) * TSTRIDE + akoff * 2;
    uint32_t aoff1 = aoff0 + 16 * TSTRIDE;
    int brow = (lane & 7) + ((lane >> 4) & 1) * 8;
    int bkoff = ((lane >> 3) & 1) * 8;
    uint32_t boff = (uint32_t)(warp_n + brow) * TSTRIDE + bkoff * 2;

    float acc[2][8][4];
#pragma unroll
    for (int mt = 0; mt < 2; mt++)
#pragma unroll
        for (int j = 0; j < 8; j++)
#pragma unroll
            for (int q = 0; q < 4; q++) acc[mt][j][q] = 0.f;

    for (int c = 0; c < 2; c++) {
        if (c) __syncthreads();   // protect smem reuse across chunks

        if (c == 0) {
            // ---- A0: direct rows (X or bnrelu(g_h))
            for (int i = t; i < 8192; i += 256) {
                int row = i >> 6, col = (i & 63) * 2;
                int gr = row0 + row;
                float2 v = make_float2(0.f, 0.f);
                if (gr < NN) v = *(const float2*)(Asrc + (size_t)gr * HIDC + col);
                if (stage) {
                    v.x = fmaxf(fmaf(v.x, s_cs[col], s_cq[col]), 0.f);
                    v.y = fmaxf(fmaf(v.y, s_cs[col + 1], s_cq[col + 1]), 0.f);
                }
                __nv_bfloat16 h0 = __float2bfloat16(v.x);
                __nv_bfloat16 h1 = __float2bfloat16(v.y);
                __nv_bfloat16 l0 = __float2bfloat16(v.x - __bfloat162float(h0));
                __nv_bfloat16 l1 = __float2bfloat16(v.y - __bfloat162float(h1));
                uint32_t off = (uint32_t)row * TSTRIDE + col * 2;
                __nv_bfloat162 hv; hv.x = h0; hv.y = h1;
                __nv_bfloat162 lv; lv.x = l0; lv.y = l1;
                *(__nv_bfloat162*)(sm + OFF_AHI + off) = hv;
                *(__nv_bfloat162*)(sm + OFF_ALO + off) = lv;
            }
        } else {
            // ---- A1: in-kernel CSR gather for this CTA's 128 rows (warp-per-row)
            float4 sc4 = make_float4(0.f, 0.f, 0.f, 0.f), sh4 = sc4;
            if (stage) {
                sc4 = *(float4*)&s_cs[lane * 4];
                sh4 = *(float4*)&s_cq[lane * 4];
            }
            for (int r = w * 16; r < w * 16 + 16; r++) {
                int gr = row0 + r;
                float4 ac = make_float4(0.f, 0.f, 0.f, 0.f);
                if (gr < NN) {
                    int j = g_rowptr[gr], end = g_rowptr[gr + 1];
                    float ndd = -g_dinv[gr];
                    for (; j + 4 <= end; j += 4) {
                        int s0 = __ldg(&g_csr_src[j]),     s1 = __ldg(&g_csr_src[j + 1]);
                        int s2 = __ldg(&g_csr_src[j + 2]), s3 = __ldg(&g_csr_src[j + 3]);
                        float w0 = ndd * __ldg(&g_csr_w[j]),     w1 = ndd * __ldg(&g_csr_w[j + 1]);
                        float w2 = ndd * __ldg(&g_csr_w[j + 2]), w3 = ndd * __ldg(&g_csr_w[j + 3]);
                        float4 v0 = ((const float4*)(Asrc + (size_t)s0 * HIDC))[lane];
                        float4 v1 = ((const float4*)(Asrc + (size_t)s1 * HIDC))[lane];
                        float4 v2 = ((const float4*)(Asrc + (size_t)s2 * HIDC))[lane];
                        float4 v3 = ((const float4*)(Asrc + (size_t)s3 * HIDC))[lane];
                        if (stage) {
                            v0.x = fmaxf(fmaf(v0.x, sc4.x, sh4.x), 0.f); v1.x = fmaxf(fmaf(v1.x, sc4.x, sh4.x), 0.f);
                            v2.x = fmaxf(fmaf(v2.x, sc4.x, sh4.x), 0.f); v3.x = fmaxf(fmaf(v3.x, sc4.x, sh4.x), 0.f);
                            v0.y = fmaxf(fmaf(v0.y, sc4.y, sh4.y), 0.f); v1.y = fmaxf(fmaf(v1.y, sc4.y, sh4.y), 0.f);
                            v2.y = fmaxf(fmaf(v2.y, sc4.y, sh4.y), 0.f); v3.y = fmaxf(fmaf(v3.y, sc4.y, sh4.y), 0.f);
                            v0.z = fmaxf(fmaf(v0.z, sc4.z, sh4.z), 0.f); v1.z = fmaxf(fmaf(v1.z, sc4.z, sh4.z), 0.f);
                            v2.z = fmaxf(fmaf(v2.z, sc4.z, sh4.z), 0.f); v3.z = fmaxf(fmaf(v3.z, sc4.z, sh4.z), 0.f);
                            v0.w = fmaxf(fmaf(v0.w, sc4.w, sh4.w), 0.f); v1.w = fmaxf(fmaf(v1.w, sc4.w, sh4.w), 0.f);
                            v2.w = fmaxf(fmaf(v2.w, sc4.w, sh4.w), 0.f); v3.w = fmaxf(fmaf(v3.w, sc4.w, sh4.w), 0.f);
                        }
                        ac.x += w0 * v0.x + w1 * v1.x + w2 * v2.x + w3 * v3.x;
                        ac.y += w0 * v0.y + w1 * v1.y + w2 * v2.y + w3 * v3.y;
                        ac.z += w0 * v0.z + w1 * v1.z + w2 * v2.z + w3 * v3.z;
                        ac.w += w0 * v0.w + w1 * v1.w + w2 * v2.w + w3 * v3.w;
                    }
                    for (; j < end; j++) {
                        int s0 = __ldg(&g_csr_src[j]);
                        float w0 = ndd * __ldg(&g_csr_w[j]);
                        float4 v0 = ((const float4*)(Asrc + (size_t)s0 * HIDC))[lane];
                        if (stage) {
                            v0.x = fmaxf(fmaf(v0.x, sc4.x, sh4.x), 0.f);
                            v0.y = fmaxf(fmaf(v0.y, sc4.y, sh4.y), 0.f);
                            v0.z = fmaxf(fmaf(v0.z, sc4.z, sh4.z), 0.f);
                            v0.w = fmaxf(fmaf(v0.w, sc4.w, sh4.w), 0.f);
                        }
                        ac.x += w0 * v0.x; ac.y += w0 * v0.y; ac.z += w0 * v0.z; ac.w += w0 * v0.w;
                    }
                }
                // convert to hi/lo bf16, write smem row r, cols [lane*4, lane*4+4)
                __nv_bfloat16 h0 = __float2bfloat16(ac.x);
                __nv_bfloat16 h1 = __float2bfloat16(ac.y);
                __nv_bfloat16 h2 = __float2bfloat16(ac.z);
                __nv_bfloat16 h3 = __float2bfloat16(ac.w);
                __nv_bfloat16 l0 = __float2bfloat16(ac.x - __bfloat162float(h0));
                __nv_bfloat16 l1 = __float2bfloat16(ac.y - __bfloat162float(h1));
                __nv_bfloat16 l2 = __float2bfloat16(ac.z - __bfloat162float(h2));
                __nv_bfloat16 l3 = __float2bfloat16(ac.w - __bfloat162float(h3));
                uint32_t off = (uint32_t)r * TSTRIDE + (uint32_t)lane * 8;
                __nv_bfloat162 p;
                p.x = h0; p.y = h1; *(__nv_bfloat162*)(sm + OFF_AHI + off) = p;
                p.x = h2; p.y = h3; *(__nv_bfloat162*)(sm + OFF_AHI + off + 4) = p;
                p.x = l0; p.y = l1; *(__nv_bfloat162*)(sm + OFF_ALO + off) = p;
                p.x = l2; p.y = l3; *(__nv_bfloat162*)(sm + OFF_ALO + off + 4) = p;
            }
        }

        // ---- B tile chunk c
        for (int i = t; i < 8192; i += 256) {
            int row = i >> 6, col = (i & 63) * 2;
            __nv_bfloat162 hv = *(const __nv_bfloat162*)(Whi + row * 256 + c * 128 + col);
            __nv_bfloat162 lv = *(const __nv_bfloat162*)(Wlo + row * 256 + c * 128 + col);
            uint32_t off = (uint32_t)row * TSTRIDE + col * 2;
            *(__nv_bfloat162*)(sm + OFF_BHI + off) = hv;
            *(__nv_bfloat162*)(sm + OFF_BLO + off) = lv;
        }
        __syncthreads();

#pragma unroll
        for (int ks = 0; ks < 8; ks++) {
            uint32_t k2 = (uint32_t)ks * 32;
            uint32_t ah0[4], ah1[4], al0[4], al1[4];
            ldsm4(ah0, sb + OFF_AHI + aoff0 + k2);
            ldsm4(ah1, sb + OFF_AHI + aoff1 + k2);
            ldsm4(al0, sb + OFF_ALO + aoff0 + k2);
            ldsm4(al1, sb + OFF_ALO + aoff1 + k2);
#pragma unroll
            for (int np = 0; np < 4; np++) {
                uint32_t bh[4], bl[4];
                uint32_t bo = boff + (uint32_t)np * 16 * TSTRIDE + k2;
                ldsm4(bh, sb + OFF_BHI + bo);
                ldsm4(bl, sb + OFF_BLO + bo);
                mma_bf16(acc[0][2 * np],     ah0, bh);
                mma_bf16(acc[0][2 * np + 1], ah0, bh + 2);
                mma_bf16(acc[1][2 * np],     ah1, bh);
                mma_bf16(acc[1][2 * np + 1], ah1, bh + 2);
                mma_bf16(acc[0][2 * np],     al0, bh);
                mma_bf16(acc[0][2 * np + 1], al0, bh + 2);
                mma_bf16(acc[1][2 * np],     al1, bh);
                mma_bf16(acc[1][2 * np + 1], al1, bh + 2);
                mma_bf16(acc[0][2 * np],     ah0, bl);
                mma_bf16(acc[0][2 * np + 1], ah0, bl + 2);
                mma_bf16(acc[1][2 * np],     ah1, bl);
                mma_bf16(acc[1][2 * np + 1], ah1, bl + 2);
            }
        }
    }

#pragma unroll
    for (int j = 0; j < 8; j++) {
        int n = warp_n + j * 8 + tig * 2;
        float b0 = bias[n], b1 = bias[n + 1];
#pragma unroll
        for (int mt = 0; mt < 2; mt++) {
            int r1 = row0 + warp_m + mt * 16 + gid;
            int r2 = r1 + 8;
            float2 v1 = make_float2(acc[mt][j][0] + b0, acc[mt][j][1] + b1);
            float2 v2 = make_float2(acc[mt][j][2] + b0, acc[mt][j][3] + b1);
            if (stage == 0) {
                if (r1 < NN) *(float2*)(g_h + (size_t)r1 * HIDC + n) = v1;
                if (r2 < NN) *(float2*)(g_h + (size_t)r2 * HIDC + n) = v2;
                float sx = (r1 < NN ? v1.x : 0.f) + (r2 < NN ? v2.x : 0.f);
                float sy = (r1 < NN ? v1.y : 0.f) + (r2 < NN ? v2.y : 0.f);
                float qx = (r1 < NN ? v1.x * v1.x : 0.f) + (r2 < NN ? v2.x * v2.x : 0.f);
                float qy = (r1 < NN ? v1.y * v1.y : 0.f) + (r2 < NN ? v2.y * v2.y : 0.f);
#pragma unroll
                for (int off = 4; off <= 16; off <<= 1) {
                    sx += __shfl_xor_sync(0xffffffffu, sx, off);
                    sy += __shfl_xor_sync(0xffffffffu, sy, off);
                    qx += __shfl_xor_sync(0xffffffffu, qx, off);
                    qy += __shfl_xor_sync(0xffffffffu, qy, off);
                }
                if (gid == 0) {
                    atomicAdd(&s_cs[n], sx);
                    atomicAdd(&s_cs[n + 1], sy);
                    atomicAdd(&s_cq[n], qx);
                    atomicAdd(&s_cq[n + 1], qy);
                }
            } else {
                int nl = (n < 64) ? n : (n - 64);
                size_t obase = (n < 64) ? 0 : (size_t)NN * OUTC;
                if (r1 < NN) *(float2*)(outExt + obase + (size_t)r1 * OUTC + nl) = v1;
                if (r2 < NN) *(float2*)(outExt + obase + (size_t)r2 * OUTC + nl) = v2;
            }
        }
    }

    if (stage == 0) {
        __syncthreads();
        if (t < 128) {
            atomicAdd(&g_sum[t], s_cs[t]);
            atomicAdd(&g_sumsq[t], s_cq[t]);
        }
    }
}

// ---------------- launch ----------------
extern "C" void kernel_launch(void* const* d_in, const int* in_sizes, int n_in,
                              void* d_out, int out_size) {
    const float* x     = (const float*)d_in[0];
    const int*   ei    = (const int*)d_in[1];
    const int*   src   = ei;
    const int*   dst   = ei + EE;
    const float* W1_0  = (const float*)d_in[2];
    const float* W1_1  = (const float*)d_in[3];
    const float* b1    = (const float*)d_in[4];
    const float* gamma = (const float*)d_in[5];
    const float* beta  = (const float*)d_in[6];
    const float* Wmu0  = (const float*)d_in[7];
    const float* Wmu1  = (const float*)d_in[8];
    const float* bmu   = (const float*)d_in[9];
    const float* Wls0  = (const float*)d_in[10];
    const float* Wls1  = (const float*)d_in[11];
    const float* bls   = (const float*)d_in[12];
    float* out = (float*)d_out;

    cudaFuncSetAttribute(k_tgemm, cudaFuncAttributeMaxDynamicSharedMemorySize, SMEM_TOT);

    k_zero_small<<<(NN + 255) / 256, 256>>>();
    k_prep<<<(EE + 255) / 256, 256>>>(src, dst);
    k_prepw<<<256, 256>>>(W1_0, W1_1, Wmu0, Wmu1, Wls0, Wls1, bmu, bls);
    k_csrprep<<<NCHUNK, 256>>>();
    k_bscan<<<1, 256>>>();
    k_chunkscan<<<NCHUNK, 256>>>();
    k_fill<<<(EE + 255) / 256, 256>>>(src, dst);
    k_tgemm<<<(NN + 127) / 128, 256, SMEM_TOT>>>(x, b1, gamma, beta, nullptr, 0);
    k_tgemm<<<(NN + 127) / 128, 256, SMEM_TOT>>>(nullptr, nullptr, gamma, beta, out, 1);
}

// round 7
// speedup vs baseline: 1.4325x; 1.4325x over previous
#include <cuda_runtime.h>
#include <cuda_bf16.h>
#include <cstdint>

#define NN 50000
#define EE 800000
#define HIDC 128
#define OUTC 64
#define EPSF 1e-5f
#define NCHUNK 196   // ceil(NN/256)

// ---------------- scratch (device globals) ----------------
__device__ float g_deg[NN];
__device__ float g_dinv[NN];
__device__ float g_tx1[(size_t)NN * HIDC];
__device__ float g_h[(size_t)NN * HIDC];
__device__ float g_th[(size_t)NN * HIDC];
__device__ float g_sum[HIDC];
__device__ float g_sumsq[HIDC];
// CSR scratch
__device__ int   g_cnt[NN];
__device__ int   g_bsum[NCHUNK];
__device__ int   g_boff[NCHUNK];
__device__ int   g_rowptr[NN + 1];
__device__ int   g_cursor[NN];
__device__ int   g_csr_src[EE];
__device__ float g_csr_w[EE];
// split-bf16 weights, pre-transposed: [N=128][K=256], K-major rows
__device__ __nv_bfloat16 g_w1hi[128 * 256];
__device__ __nv_bfloat16 g_w1lo[128 * 256];
__device__ __nv_bfloat16 g_w2hi[128 * 256];
__device__ __nv_bfloat16 g_w2lo[128 * 256];
__device__ float g_bias2[128];

// ---------------- mma / ldmatrix helpers ----------------
__device__ __forceinline__ uint32_t smem_u32(const void* p) {
    uint32_t a;
    asm("{ .reg .u64 t; cvta.to.shared.u64 t, %1; cvt.u32.u64 %0, t; }" : "=r"(a) : "l"(p));
    return a;
}
__device__ __forceinline__ void ldsm4(uint32_t* r, uint32_t addr) {
    asm volatile("ldmatrix.sync.aligned.m8n8.x4.shared.b16 {%0,%1,%2,%3}, [%4];"
                 : "=r"(r[0]), "=r"(r[1]), "=r"(r[2]), "=r"(r[3]) : "r"(addr));
}
__device__ __forceinline__ void mma_bf16(float* c, const uint32_t* a, const uint32_t* b) {
    asm volatile("mma.sync.aligned.m16n8k16.row.col.f32.bf16.bf16.f32 "
                 "{%0,%1,%2,%3}, {%4,%5,%6,%7}, {%8,%9}, {%0,%1,%2,%3};"
                 : "+f"(c[0]), "+f"(c[1]), "+f"(c[2]), "+f"(c[3])
                 : "r"(a[0]), "r"(a[1]), "r"(a[2]), "r"(a[3]), "r"(b[0]), "r"(b[1]));
}

// ---------------- prep kernels (self-cleaning; no separate zero pass) ----------------
__global__ void k_prep(const int* __restrict__ src, const int* __restrict__ dst) {
    int e = blockIdx.x * blockDim.x + threadIdx.x;
    if (blockIdx.x == 0 && threadIdx.x < 128) {
        g_sum[threadIdx.x] = 0.f;       // consumed by tgemm0 (later in chain)
        g_sumsq[threadIdx.x] = 0.f;
    }
    if (e < EE) {
        atomicAdd(&g_deg[src[e]], 1.0f);
        atomicAdd(&g_cnt[dst[e]], 1);
    }
}

// fused: dinv + per-chunk count sums; zeroes g_deg for next replay
__global__ void k_csrprep() {
    __shared__ int s[256];
    int c = blockIdx.x * 256 + threadIdx.x;
    int v = 0;
    if (c < NN) {
        v = g_cnt[c];
        float d = g_deg[c];
        g_dinv[c] = (d > 0.5f) ? rsqrtf(d) : 0.f;
        g_deg[c] = 0.f;
    }
    s[threadIdx.x] = v;
    __syncthreads();
    for (int off = 128; off > 0; off >>= 1) {
        if (threadIdx.x < off) s[threadIdx.x] += s[threadIdx.x + off];
        __syncthreads();
    }
    if (threadIdx.x == 0) g_bsum[blockIdx.x] = s[0];
}

__global__ void k_bscan() {
    __shared__ int s[256];
    int t = threadIdx.x;
    int v = (t < NCHUNK) ? g_bsum[t] : 0;
    s[t] = v;
    __syncthreads();
    for (int off = 1; off < 256; off <<= 1) {
        int u = (t >= off) ? s[t - off] : 0;
        __syncthreads();
        s[t] += u;
        __syncthreads();
    }
    if (t < NCHUNK) g_boff[t] = s[t] - v;
    if (t == 0) g_rowptr[NN] = EE;
}

// zeroes g_cnt for next replay
__global__ void k_chunkscan() {
    __shared__ int s[256];
    int c = blockIdx.x * 256 + threadIdx.x;
    int v = (c < NN) ? g_cnt[c] : 0;
    s[threadIdx.x] = v;
    __syncthreads();
    for (int off = 1; off < 256; off <<= 1) {
        int t = (threadIdx.x >= off) ? s[threadIdx.x - off] : 0;
        __syncthreads();
        s[threadIdx.x] += t;
        __syncthreads();
    }
    if (c < NN) {
        int excl = g_boff[blockIdx.x] + s[threadIdx.x] - v;
        g_rowptr[c] = excl;
        g_cursor[c] = excl;
        g_cnt[c] = 0;
    }
}

__global__ void k_fill(const int* __restrict__ src, const int* __restrict__ dst) {
    int e = blockIdx.x * blockDim.x + threadIdx.x;
    if (e < EE) {
        int s = src[e], d = dst[e];
        int p = atomicAdd(&g_cursor[d], 1);
        g_csr_src[p] = s;
        g_csr_w[p] = g_dinv[s];
    }
}

// ---------------- weight prep: transpose + split to bf16 hi/lo ----------------
__global__ void k_prepw(const float* __restrict__ W1_0, const float* __restrict__ W1_1,
                        const float* __restrict__ Wmu0, const float* __restrict__ Wmu1,
                        const float* __restrict__ Wls0, const float* __restrict__ Wls1,
                        const float* __restrict__ bmu, const float* __restrict__ bls) {
    int idx = blockIdx.x * blockDim.x + threadIdx.x;
    if (idx < 65536) {
        int stage = idx >> 15;
        int r = idx & 32767;
        int j = r >> 8, k = r & 255;
        float w;
        if (stage == 0) {
            w = (k < 128) ? W1_0[k * HIDC + j] : W1_1[(k - 128) * HIDC + j];
        } else {
            if (j < 64) w = (k < 128) ? Wmu0[k * OUTC + j] : Wmu1[(k - 128) * OUTC + j];
            else        w = (k < 128) ? Wls0[k * OUTC + (j - 64)] : Wls1[(k - 128) * OUTC + (j - 64)];
        }
        __nv_bfloat16 hi = __float2bfloat16(w);
        __nv_bfloat16 lo = __float2bfloat16(w - __bfloat162float(hi));
        if (stage == 0) { g_w1hi[r] = hi; g_w1lo[r] = lo; }
        else            { g_w2hi[r] = hi; g_w2lo[r] = lo; }
    }
    if (blockIdx.x == 0 && threadIdx.x < 128) {
        int j = threadIdx.x;
        g_bias2[j] = (j < 64) ? bmu[j] : bls[j - 64];
    }
}

// ---------------- gather 1 (unroll 8 = two independent groups of 4) ----------------
__global__ void k_gather1(const float* __restrict__ X) {
    int warp = (int)(((size_t)blockIdx.x * blockDim.x + threadIdx.x) >> 5);
    if (warp >= NN) return;
    int lane = threadIdx.x & 31;
    int d = warp;
    int j = g_rowptr[d], end = g_rowptr[d + 1];
    float ndd = -g_dinv[d];
    float4 acc = make_float4(0.f, 0.f, 0.f, 0.f);
    float4 acc2 = make_float4(0.f, 0.f, 0.f, 0.f);
    for (; j + 8 <= end; j += 8) {
        int s0 = __ldg(&g_csr_src[j]),     s1 = __ldg(&g_csr_src[j + 1]);
        int s2 = __ldg(&g_csr_src[j + 2]), s3 = __ldg(&g_csr_src[j + 3]);
        int s4 = __ldg(&g_csr_src[j + 4]), s5 = __ldg(&g_csr_src[j + 5]);
        int s6 = __ldg(&g_csr_src[j + 6]), s7 = __ldg(&g_csr_src[j + 7]);
        float w0 = ndd * __ldg(&g_csr_w[j]),     w1 = ndd * __ldg(&g_csr_w[j + 1]);
        float w2 = ndd * __ldg(&g_csr_w[j + 2]), w3 = ndd * __ldg(&g_csr_w[j + 3]);
        float w4 = ndd * __ldg(&g_csr_w[j + 4]), w5 = ndd * __ldg(&g_csr_w[j + 5]);
        float w6 = ndd * __ldg(&g_csr_w[j + 6]), w7 = ndd * __ldg(&g_csr_w[j + 7]);
        float4 v0 = ((const float4*)(X + (size_t)s0 * HIDC))[lane];
        float4 v1 = ((const float4*)(X + (size_t)s1 * HIDC))[lane];
        float4 v2 = ((const float4*)(X + (size_t)s2 * HIDC))[lane];
        float4 v3 = ((const float4*)(X + (size_t)s3 * HIDC))[lane];
        float4 v4 = ((const float4*)(X + (size_t)s4 * HIDC))[lane];
        float4 v5 = ((const float4*)(X + (size_t)s5 * HIDC))[lane];
        float4 v6 = ((const float4*)(X + (size_t)s6 * HIDC))[lane];
        float4 v7 = ((const float4*)(X + (size_t)s7 * HIDC))[lane];
        acc.x  += w0 * v0.x + w1 * v1.x + w2 * v2.x + w3 * v3.x;
        acc.y  += w0 * v0.y + w1 * v1.y + w2 * v2.y + w3 * v3.y;
        acc.z  += w0 * v0.z + w1 * v1.z + w2 * v2.z + w3 * v3.z;
        acc.w  += w0 * v0.w + w1 * v1.w + w2 * v2.w + w3 * v3.w;
        acc2.x += w4 * v4.x + w5 * v5.x + w6 * v6.x + w7 * v7.x;
        acc2.y += w4 * v4.y + w5 * v5.y + w6 * v6.y + w7 * v7.y;
        acc2.z += w4 * v4.z + w5 * v5.z + w6 * v6.z + w7 * v7.z;
        acc2.w += w4 * v4.w + w5 * v5.w + w6 * v6.w + w7 * v7.w;
    }
    for (; j < end; j++) {
        int s0 = __ldg(&g_csr_src[j]);
        float w0 = ndd * __ldg(&g_csr_w[j]);
        float4 v0 = ((const float4*)(X + (size_t)s0 * HIDC))[lane];
        acc.x += w0 * v0.x; acc.y += w0 * v0.y; acc.z += w0 * v0.z; acc.w += w0 * v0.w;
    }
    acc.x += acc2.x; acc.y += acc2.y; acc.z += acc2.z; acc.w += acc2.w;
    ((float4*)(g_tx1 + (size_t)d * HIDC))[lane] = acc;
}

// ---------------- gather 2 (fused BN scale/shift; unroll 8) ----------------
__global__ void __launch_bounds__(256) k_gather2(const float* __restrict__ gamma,
                                                 const float* __restrict__ beta) {
    __shared__ float s_sc[128], s_sh[128];
    int t = threadIdx.x;
    if (t < 128) {
        float mean = g_sum[t] * (1.0f / NN);
        float var = fmaxf(g_sumsq[t] * (1.0f / NN) - mean * mean, 0.f);
        float sc = gamma[t] * rsqrtf(var + EPSF);
        s_sc[t] = sc;
        s_sh[t] = beta[t] - mean * sc;
    }
    __syncthreads();

    int warp = (int)(((size_t)blockIdx.x * blockDim.x + t) >> 5);
    if (warp >= NN) return;
    int lane = t & 31;
    int d = warp;
    int j = g_rowptr[d], end = g_rowptr[d + 1];
    float ndd = -g_dinv[d];
    float4 sc = *(float4*)&s_sc[lane * 4];
    float4 sh = *(float4*)&s_sh[lane * 4];
    float4 acc = make_float4(0.f, 0.f, 0.f, 0.f);
    float4 acc2 = make_float4(0.f, 0.f, 0.f, 0.f);
#define BNR(v) \
    v.x = fmaxf(fmaf(v.x, sc.x, sh.x), 0.f); \
    v.y = fmaxf(fmaf(v.y, sc.y, sh.y), 0.f); \
    v.z = fmaxf(fmaf(v.z, sc.z, sh.z), 0.f); \
    v.w = fmaxf(fmaf(v.w, sc.w, sh.w), 0.f)
    for (; j + 8 <= end; j += 8) {
        int s0 = __ldg(&g_csr_src[j]),     s1 = __ldg(&g_csr_src[j + 1]);
        int s2 = __ldg(&g_csr_src[j + 2]), s3 = __ldg(&g_csr_src[j + 3]);
        int s4 = __ldg(&g_csr_src[j + 4]), s5 = __ldg(&g_csr_src[j + 5]);
        int s6 = __ldg(&g_csr_src[j + 6]), s7 = __ldg(&g_csr_src[j + 7]);
        float w0 = ndd * __ldg(&g_csr_w[j]),     w1 = ndd * __ldg(&g_csr_w[j + 1]);
        float w2 = ndd * __ldg(&g_csr_w[j + 2]), w3 = ndd * __ldg(&g_csr_w[j + 3]);
        float w4 = ndd * __ldg(&g_csr_w[j + 4]), w5 = ndd * __ldg(&g_csr_w[j + 5]);
        float w6 = ndd * __ldg(&g_csr_w[j + 6]), w7 = ndd * __ldg(&g_csr_w[j + 7]);
        float4 v0 = ((const float4*)(g_h + (size_t)s0 * HIDC))[lane];
        float4 v1 = ((const float4*)(g_h + (size_t)s1 * HIDC))[lane];
        float4 v2 = ((const float4*)(g_h + (size_t)s2 * HIDC))[lane];
        float4 v3 = ((const float4*)(g_h + (size_t)s3 * HIDC))[lane];
        float4 v4 = ((const float4*)(g_h + (size_t)s4 * HIDC))[lane];
        float4 v5 = ((const float4*)(g_h + (size_t)s5 * HIDC))[lane];
        float4 v6 = ((const float4*)(g_h + (size_t)s6 * HIDC))[lane];
        float4 v7 = ((const float4*)(g_h + (size_t)s7 * HIDC))[lane];
        BNR(v0); BNR(v1); BNR(v2); BNR(v3); BNR(v4); BNR(v5); BNR(v6); BNR(v7);
        acc.x  += w0 * v0.x + w1 * v1.x + w2 * v2.x + w3 * v3.x;
        acc.y  += w0 * v0.y + w1 * v1.y + w2 * v2.y + w3 * v3.y;
        acc.z  += w0 * v0.z + w1 * v1.z + w2 * v2.z + w3 * v3.z;
        acc.w  += w0 * v0.w + w1 * v1.w + w2 * v2.w + w3 * v3.w;
        acc2.x += w4 * v4.x + w5 * v5.x + w6 * v6.x + w7 * v7.x;
        acc2.y += w4 * v4.y + w5 * v5.y + w6 * v6.y + w7 * v7.y;
        acc2.z += w4 * v4.z + w5 * v5.z + w6 * v6.z + w7 * v7.z;
        acc2.w += w4 * v4.w + w5 * v5.w + w6 * v6.w + w7 * v7.w;
    }
    for (; j < end; j++) {
        int s0 = __ldg(&g_csr_src[j]);
        float w0 = ndd * __ldg(&g_csr_w[j]);
        float4 v0 = ((const float4*)(g_h + (size_t)s0 * HIDC))[lane];
        BNR(v0);
        acc.x += w0 * v0.x; acc.y += w0 * v0.y; acc.z += w0 * v0.z; acc.w += w0 * v0.w;
    }
#undef BNR
    acc.x += acc2.x; acc.y += acc2.y; acc.z += acc2.z; acc.w += acc2.w;
    ((float4*)(g_th + (size_t)d * HIDC))[lane] = acc;
}

// ---------------- HMMA split-bf16 GEMM, K in 4 chunks of 64 (smem 72KB -> 2 CTAs/SM) ----------------
// chunk 0,1: A-source direct rows (X or bnrelu(g_h)); chunk 2,3: g_tx1 / g_th
#define TSTRIDE 144                     // 64 bf16 = 128B + 16B pad
#define TILE_B (128 * TSTRIDE)          // 18432
#define OFF_AHI 0
#define OFF_ALO TILE_B
#define OFF_BHI (2 * TILE_B)
#define OFF_BLO (3 * TILE_B)
#define SMEM_TOT (4 * TILE_B)           // 73728

__global__ void __launch_bounds__(256, 2) k_tgemm(const float* __restrict__ Xext,
                                                  const float* __restrict__ biasExt,
                                                  const float* __restrict__ gamma,
                                                  const float* __restrict__ beta,
                                                  float* __restrict__ outExt, int stage) {
    extern __shared__ char sm[];
    __shared__ float s_cs[128], s_cq[128];   // stage0: col sums; stage1: scale/shift
    uint32_t sb = smem_u32(sm);
    int t = threadIdx.x;
    int row0 = blockIdx.x * 128;

    if (stage == 0) {
        if (t < 128) { s_cs[t] = 0.f; s_cq[t] = 0.f; }
    } else {
        if (t < 128) {
            float mean = g_sum[t] * (1.0f / NN);
            float var = fmaxf(g_sumsq[t] * (1.0f / NN) - mean * mean, 0.f);
            float sc = gamma[t] * rsqrtf(var + EPSF);
            s_cs[t] = sc;
            s_cq[t] = beta[t] - mean * sc;
        }
        __syncthreads();
    }

    const float* A0 = stage ? g_h : Xext;
    const float* A1 = stage ? g_th : g_tx1;
    const __nv_bfloat16* Whi = stage ? g_w2hi : g_w1hi;
    const __nv_bfloat16* Wlo = stage ? g_w2lo : g_w1lo;
    const float* bias = stage ? g_bias2 : biasExt;

    int w = t >> 5, lane = t & 31;
    int warp_m = (w >> 1) * 32, warp_n = (w & 1) * 64;
    int gid = lane >> 2, tig = lane & 3;

    int arow = (lane & 7) + ((lane >> 3) & 1) * 8;
    int akoff = (lane >> 4) * 8;
    uint32_t aoff0 = (uint32_t)(warp_m + arow) * TSTRIDE + akoff * 2;
    uint32_t aoff1 = aoff0 + 16 * TSTRIDE;
    int brow = (lane & 7) + ((lane >> 4) & 1) * 8;
    int bkoff = ((lane >> 3) & 1) * 8;
    uint32_t boff = (uint32_t)(warp_n + brow) * TSTRIDE + bkoff * 2;

    float acc[2][8][4];
#pragma unroll
    for (int mt = 0; mt < 2; mt++)
#pragma unroll
        for (int j = 0; j < 8; j++)
#pragma unroll
            for (int q = 0; q < 4; q++) acc[mt][j][q] = 0.f;

    for (int kc = 0; kc < 4; kc++) {
        if (kc) __syncthreads();
        const float* A = (kc < 2) ? A0 : A1;
        int colbase = (kc & 1) * 64;
        bool bn = (stage == 1) && (kc < 2);
        // ---- A chunk: 128 rows x 64 cols fp32 -> hi/lo bf16
        for (int i = t; i < 4096; i += 256) {
            int row = i >> 5, c2 = (i & 31) * 2;
            int gr = row0 + row;
            float2 v = make_float2(0.f, 0.f);
            if (gr < NN) v = *(const float2*)(A + (size_t)gr * HIDC + colbase + c2);
            if (bn) {
                int col = colbase + c2;
                v.x = fmaxf(fmaf(v.x, s_cs[col], s_cq[col]), 0.f);
                v.y = fmaxf(fmaf(v.y, s_cs[col + 1], s_cq[col + 1]), 0.f);
            }
            __nv_bfloat16 h0 = __float2bfloat16(v.x);
            __nv_bfloat16 h1 = __float2bfloat16(v.y);
            __nv_bfloat16 l0 = __float2bfloat16(v.x - __bfloat162float(h0));
            __nv_bfloat16 l1 = __float2bfloat16(v.y - __bfloat162float(h1));
            uint32_t off = (uint32_t)row * TSTRIDE + c2 * 2;
            __nv_bfloat162 hv; hv.x = h0; hv.y = h1;
            __nv_bfloat162 lv; lv.x = l0; lv.y = l1;
            *(__nv_bfloat162*)(sm + OFF_AHI + off) = hv;
            *(__nv_bfloat162*)(sm + OFF_ALO + off) = lv;
        }
        // ---- B chunk: 128 n-rows x 64 k-cols (k global = kc*64 + c2)
        for (int i = t; i < 4096; i += 256) {
            int n = i >> 5, c2 = (i & 31) * 2;
            __nv_bfloat162 hv = *(const __nv_bfloat162*)(Whi + n * 256 + kc * 64 + c2);
            __nv_bfloat162 lv = *(const __nv_bfloat162*)(Wlo + n * 256 + kc * 64 + c2);
            uint32_t off = (uint32_t)n * TSTRIDE + c2 * 2;
            *(__nv_bfloat162*)(sm + OFF_BHI + off) = hv;
            *(__nv_bfloat162*)(sm + OFF_BLO + off) = lv;
        }
        __syncthreads();

#pragma unroll
        for (int ks = 0; ks < 4; ks++) {
            uint32_t k2 = (uint32_t)ks * 32;
            uint32_t ah0[4], ah1[4], al0[4], al1[4];
            ldsm4(ah0, sb + OFF_AHI + aoff0 + k2);
            ldsm4(ah1, sb + OFF_AHI + aoff1 + k2);
            ldsm4(al0, sb + OFF_ALO + aoff0 + k2);
            ldsm4(al1, sb + OFF_ALO + aoff1 + k2);
#pragma unroll
            for (int np = 0; np < 4; np++) {
                uint32_t bh[4], bl[4];
                uint32_t bo = boff + (uint32_t)np * 16 * TSTRIDE + k2;
                ldsm4(bh, sb + OFF_BHI + bo);
                ldsm4(bl, sb + OFF_BLO + bo);
                mma_bf16(acc[0][2 * np],     ah0, bh);
                mma_bf16(acc[0][2 * np + 1], ah0, bh + 2);
                mma_bf16(acc[1][2 * np],     ah1, bh);
                mma_bf16(acc[1][2 * np + 1], ah1, bh + 2);
                mma_bf16(acc[0][2 * np],     al0, bh);
                mma_bf16(acc[0][2 * np + 1], al0, bh + 2);
                mma_bf16(acc[1][2 * np],     al1, bh);
                mma_bf16(acc[1][2 * np + 1], al1, bh + 2);
                mma_bf16(acc[0][2 * np],     ah0, bl);
                mma_bf16(acc[0][2 * np + 1], ah0, bl + 2);
                mma_bf16(acc[1][2 * np],     ah1, bl);
                mma_bf16(acc[1][2 * np + 1], ah1, bl + 2);
            }
        }
    }

#pragma unroll
    for (int j = 0; j < 8; j++) {
        int n = warp_n + j * 8 + tig * 2;
        float b0 = bias[n], b1 = bias[n + 1];
#pragma unroll
        for (int mt = 0; mt < 2; mt++) {
            int r1 = row0 + warp_m + mt * 16 + gid;
            int r2 = r1 + 8;
            float2 v1 = make_float2(acc[mt][j][0] + b0, acc[mt][j][1] + b1);
            float2 v2 = make_float2(acc[mt][j][2] + b0, acc[mt][j][3] + b1);
            if (stage == 0) {
                if (r1 < NN) *(float2*)(g_h + (size_t)r1 * HIDC + n) = v1;
                if (r2 < NN) *(float2*)(g_h + (size_t)r2 * HIDC + n) = v2;
                float sx = (r1 < NN ? v1.x : 0.f) + (r2 < NN ? v2.x : 0.f);
                float sy = (r1 < NN ? v1.y : 0.f) + (r2 < NN ? v2.y : 0.f);
                float qx = (r1 < NN ? v1.x * v1.x : 0.f) + (r2 < NN ? v2.x * v2.x : 0.f);
                float qy = (r1 < NN ? v1.y * v1.y : 0.f) + (r2 < NN ? v2.y * v2.y : 0.f);
#pragma unroll
                for (int off = 4; off <= 16; off <<= 1) {
                    sx += __shfl_xor_sync(0xffffffffu, sx, off);
                    sy += __shfl_xor_sync(0xffffffffu, sy, off);
                    qx += __shfl_xor_sync(0xffffffffu, qx, off);
                    qy += __shfl_xor_sync(0xffffffffu, qy, off);
                }
                if (gid == 0) {
                    atomicAdd(&s_cs[n], sx);
                    atomicAdd(&s_cs[n + 1], sy);
                    atomicAdd(&s_cq[n], qx);
                    atomicAdd(&s_cq[n + 1], qy);
                }
            } else {
                int nl = (n < 64) ? n : (n - 64);
                size_t obase = (n < 64) ? 0 : (size_t)NN * OUTC;
                if (r1 < NN) *(float2*)(outExt + obase + (size_t)r1 * OUTC + nl) = v1;
                if (r2 < NN) *(float2*)(outExt + obase + (size_t)r2 * OUTC + nl) = v2;
            }
        }
    }

    if (stage == 0) {
        __syncthreads();
        if (t < 128) {
            atomicAdd(&g_sum[t], s_cs[t]);
            atomicAdd(&g_sumsq[t], s_cq[t]);
        }
    }
}

// ---------------- launch ----------------
extern "C" void kernel_launch(void* const* d_in, const int* in_sizes, int n_in,
                              void* d_out, int out_size) {
    const float* x     = (const float*)d_in[0];
    const int*   ei    = (const int*)d_in[1];
    const int*   src   = ei;
    const int*   dst   = ei + EE;
    const float* W1_0  = (const float*)d_in[2];
    const float* W1_1  = (const float*)d_in[3];
    const float* b1    = (const float*)d_in[4];
    const float* gamma = (const float*)d_in[5];
    const float* beta  = (const float*)d_in[6];
    const float* Wmu0  = (const float*)d_in[7];
    const float* Wmu1  = (const float*)d_in[8];
    const float* bmu   = (const float*)d_in[9];
    const float* Wls0  = (const float*)d_in[10];
    const float* Wls1  = (const float*)d_in[11];
    const float* bls   = (const float*)d_in[12];
    float* out = (float*)d_out;

    cudaFuncSetAttribute(k_tgemm, cudaFuncAttributeMaxDynamicSharedMemorySize, SMEM_TOT);

    k_prep<<<(EE + 255) / 256, 256>>>(src, dst);
    k_prepw<<<256, 256>>>(W1_0, W1_1, Wmu0, Wmu1, Wls0, Wls1, bmu, bls);
    k_csrprep<<<NCHUNK, 256>>>();
    k_bscan<<<1, 256>>>();
    k_chunkscan<<<NCHUNK, 256>>>();
    k_fill<<<(EE + 255) / 256, 256>>>(src, dst);
    k_gather1<<<(NN * 32 + 255) / 256, 256>>>(x);
    k_tgemm<<<(NN + 127) / 128, 256, SMEM_TOT>>>(x, b1, gamma, beta, nullptr, 0);
    k_gather2<<<(NN * 32 + 255) / 256, 256>>>(gamma, beta);
    k_tgemm<<<(NN + 127) / 128, 256, SMEM_TOT>>>(nullptr, nullptr, gamma, beta, out, 1);
}